// round 6
// baseline (speedup 1.0000x reference)
#include <cuda_runtime.h>
#include <cuda_bf16.h>

#define FULL 0xffffffffu
#define NEGV -1000000000.0f

// Problem shape (fixed): B=64, N=128, L=32
#define BB    64
#define NN_   128
#define LL    32
#define NN2   (NN_ * NN_)            /* 16384 cells per batch */
#define CELLS (BB * NN2)             /* 1,048,576 cells        */
#define K1_CPW 16                    /* cells per warp in K1   */
#define K1_WPB 16                    /* warps per K1 block     */
#define K1_CPB (K1_CPW * K1_WPB)     /* 256 cells per block    */
#define K1_BLOCKS (CELLS / K1_CPB)   /* 4096                   */
#define PARTS (NN2 / K1_CPB)         /* 64 gold partials per batch */
#define PP    129                    /* A/B pitch: odd -> conflict-free everywhere */

// ---------------- device scratch (no allocations allowed) ----------------
__device__ float g_pot[CELLS];            // row-major pot[b][i][j] (upper triangle valid)
__device__ float g_goldpart[BB * PARTS];  // per-block gold partial sums
__device__ float g_margin[BB];
__device__ unsigned g_count;              // wrapping completion counter (replay-safe)

// float <-> monotonic u32 key for redux.sync.max.u32
__device__ __forceinline__ unsigned f2key(float x) {
    int i = __float_as_int(x);
    return (unsigned)i ^ ((unsigned)(i >> 31) | 0x80000000u);
}
__device__ __forceinline__ float key2f(unsigned k) {
    unsigned u = (k & 0x80000000u) ? (k ^ 0x80000000u) : ~k;
    return __int_as_float((int)u);
}

// ---------------- K1: pot (row-major, upper tri only) + gold partials ----------------
// One warp per 16 consecutive cells (one (b,i) row segment; lane == label, L==32).
//   pot  = max_l(x_l + (l==g ? 0:1)) - x_0      (subtraction moved to store lane)
//   gold = x_g - x_0
// The -1e9 augment on (b,0,len-1,0) is patched in K2 (smem).
__global__ void __launch_bounds__(512) k1_pot(const float* __restrict__ logits,
                                              const void* __restrict__ labels) {
    const int warp = threadIdx.x >> 5;
    const int lane = threadIdx.x & 31;

    // labels dtype detection (uniform, deterministic): int64 values lie in [-100,32)
    long long v0 = ((const long long*)labels)[lane];
    const bool lab64 = (__ballot_sync(FULL, v0 >= -100 && v0 < 32) == FULL);

    const int c0 = (blockIdx.x * K1_WPB + warp) * K1_CPW;
    int labv = 0;
    if (lane < K1_CPW) {
        labv = lab64 ? (int)((const long long*)labels)[c0 + lane]
                     : ((const int*)labels)[c0 + lane];
        if (labv < 0) labv = 0;
    }

    // front-batched loads (MLP = 16, 2KB contiguous per warp)
    float x[K1_CPW];
    const float* base = logits + (size_t)c0 * LL;
#pragma unroll
    for (int q = 0; q < K1_CPW; ++q) x[q] = base[q * LL + lane];

    const int ii = (c0 >> 7) & 127;   // all 16 cells share row ii
    const int j0 = c0 & 127;

    float golds = 0.0f, potq = 0.0f;
#pragma unroll
    for (int q = 0; q < K1_CPW; ++q) {
        int   g  = __shfl_sync(FULL, labv, q);
        float m0 = __shfl_sync(FULL, x[q], 0);
        golds += __shfl_sync(FULL, x[q], g) - m0;
        if (j0 + q >= ii) {                        // upper triangle only (warp-uniform)
            float cand = x[q] + (lane == g ? 0.0f : 1.0f);
            unsigned r = __reduce_max_sync(FULL, f2key(cand));
            if (lane == q) potq = key2f(r) - m0;
        }
    }
    if (lane < K1_CPW && j0 + lane >= ii) g_pot[c0 + lane] = potq;  // coalesced 64B

    __shared__ float sh[K1_WPB];
    if (lane == 0) sh[warp] = golds;               // golds is warp-uniform
    __syncthreads();
    if (threadIdx.x == 0) {
        float s = 0.0f;
#pragma unroll
        for (int t = 0; t < K1_WPB; ++t) s += sh[t];   // fixed order -> deterministic
        g_goldpart[blockIdx.x] = s;                     // blockIdx = b*PARTS + local
    }
}

// ---------------- K2: per-batch max-plus CKY ----------------
// A[i][k] holds: pot[i][i+k] (preload) until width k, beta(i,k) after.
// B[j][c] holds: pot[j-127+c][j] (preload) until width 127-c, beta after.
// update: new(i,w) = (max over k<w of A[i][k] + B[i+w][(128-w)+k]) + bp[-1]
// where bp[-1] = B[i+w][127-w] still holds pot[i][i+w] at that moment.
// 512 threads; each warp handles 2 rows (i, i+16) with 16-lane k-split.
// PP=129: every LDS pattern provably conflict-free; loop guards -> no OOB reads.
__global__ void __launch_bounds__(512) k2_cky(const float* __restrict__ logits,
                                              const void* __restrict__ labels,
                                              float* __restrict__ out) {
    extern __shared__ float smem[];
    float* A = smem;               // NN_ * PP floats
    float* B = smem + NN_ * PP;    // NN_ * PP floats
    __shared__ float red[PARTS];

    const int b   = blockIdx.x;
    const int tid = threadIdx.x;
    const int wid  = tid >> 5;
    const int lane = tid & 31;

    long long v = ((const long long*)labels)[lane];
    const bool lab64 = (__ballot_sync(FULL, v >= -100 && v < 32) == FULL);

    // sequence length = count(labels[b,0,:] != -100)
    int pflag = 0;
    if (tid < NN_) {
        size_t idx = ((size_t)b << 14) + tid;
        int lab = lab64 ? (int)((const long long*)labels)[idx]
                        : ((const int*)labels)[idx];
        pflag = (lab != -100);
    }
    const int len = __syncthreads_count(pflag);

    if (tid < PARTS) red[tid] = g_goldpart[b * PARTS + tid];

    // ---- stage A[i][k] = pot[i][i+k] (coalesced gmem reads) ----
    const float* potb = g_pot + ((size_t)b << 14);
    for (int t = tid; t < NN2; t += 512) {
        int i = t >> 7, k = t & 127;
        float vv = NEGV;
        if (i + k < NN_) vv = potb[(i << 7) + i + k];
        A[i * PP + k] = vv;
    }
    __syncthreads();

    // ---- build B[j][c] = A[j-127+c][127-c] (conflict-free diagonal schedule) ----
    for (int t = tid; t < NN2; t += 512) {
        int c = t >> 7, j = t & 127;      // c fixed per chunk, j varies with lane
        int i = j - 127 + c;
        B[j * PP + c] = (i >= 0) ? A[i * PP + (127 - c)] : NEGV;
    }
    __syncthreads();

    // ---- patch pot[b,0,len-1] with the extra -1e9 augment on label 0 ----
    if (tid < 32) {
        const int j = len - 1;
        size_t cell = ((size_t)b << 14) + j;
        int g = lab64 ? (int)((const long long*)labels)[cell]
                      : ((const int*)labels)[cell];
        if (g < 0) g = 0;
        float xx = logits[cell * LL + tid];
        float m0 = __shfl_sync(FULL, xx, 0);
        float cand = (xx - m0) + (tid == g ? 0.0f : 1.0f)
                               + (tid == 0 ? NEGV : 0.0f);
#pragma unroll
        for (int o = 16; o > 0; o >>= 1)
            cand = fmaxf(cand, __shfl_xor_sync(FULL, cand, o));
        if (tid == 0) {
            A[j]                 = cand;   // A[0][len-1]
            B[j * PP + 127 - j]  = cand;   // B[len-1][128-len]
        }
    }
    __syncthreads();

    // ---- width loop ----
    const int half   = lane >> 4;                 // 0 or 1
    const int kb     = lane & 15;
    const unsigned hmask = half ? 0xFFFF0000u : 0x0000FFFFu;
    const int ibase  = wid + (half << 4);         // 0..31

    for (int w = 1; w < NN_; ++w) {
        const int rmax = NN_ - w;
#pragma unroll
        for (int r = 0; r < 4; ++r) {
            const int i = ibase + (r << 5);
            if (i < rmax) {                       // uniform within each half-warp
                const float* Ar = A + i * PP;
                const float* bp = B + (i + w) * PP + (NN_ - w);
                float potv = bp[-1];              // preloaded pot[i][i+w]
                float a0 = -1e30f, a1 = -1e30f;
                int k = kb;
                while (k + 16 < w) {
                    a0 = fmaxf(a0, Ar[k]      + bp[k]);
                    a1 = fmaxf(a1, Ar[k + 16] + bp[k + 16]);
                    k += 32;
                }
                if (k < w) a0 = fmaxf(a0, Ar[k] + bp[k]);
                unsigned m = __reduce_max_sync(hmask, f2key(fmaxf(a0, a1)));
                float nv = key2f(m) + potv;
                if (kb == 0)      A[i * PP + w]            = nv;
                else if (kb == 1) B[(i + w) * PP + 127 - w] = nv;
            }
        }
        __syncthreads();
    }

    // ---- margin + deterministic final reduce ----
    if (tid == 0) {
        float gold = 0.0f;
#pragma unroll
        for (int t = 0; t < PARTS; ++t) gold += red[t];   // fixed order
        float pred = A[len - 1];                          // beta(0, len-1)
        g_margin[b] = fmaxf(pred - gold, 0.0f);
        __threadfence();
        unsigned old = atomicInc(&g_count, BB - 1);       // wraps -> replay/graph-safe
        if (old == BB - 1) {                              // last block: fixed-order mean
            float s = 0.0f;
            volatile float* gm = g_margin;
#pragma unroll
            for (int t = 0; t < BB; ++t) s += gm[t];
            out[0] = s * (1.0f / (float)BB);
        }
    }
}

// ---------------- launch ----------------
extern "C" void kernel_launch(void* const* d_in, const int* in_sizes, int n_in,
                              void* d_out, int out_size) {
    const float* logits = (const float*)d_in[0];
    const void*  labels = d_in[1];

    const int smem_bytes = 2 * NN_ * PP * (int)sizeof(float);   // 132,096
    cudaFuncSetAttribute(k2_cky, cudaFuncAttributeMaxDynamicSharedMemorySize, smem_bytes);

    k1_pot<<<K1_BLOCKS, 512>>>(logits, labels);
    k2_cky<<<BB, 512, smem_bytes>>>(logits, labels, (float*)d_out);
}

// round 7
// speedup vs baseline: 1.5561x; 1.5561x over previous
#include <cuda_runtime.h>
#include <cuda_bf16.h>

#define FULL 0xffffffffu
#define NEGV -1000000000.0f

// Problem shape (fixed): B=64, N=128, L=32
#define BB    64
#define NN_   128
#define LL    32
#define NN2   (NN_ * NN_)            /* 16384 cells per batch */
#define CELLS (BB * NN2)             /* 1,048,576 cells        */
#define K1_CPW 16                    /* cells per warp in K1   */
#define K1_WPB 16                    /* warps per K1 block     */
#define K1_CPB (K1_CPW * K1_WPB)     /* 256 cells per block    */
#define K1_BLOCKS (CELLS / K1_CPB)   /* 4096                   */
#define PARTS (NN2 / K1_CPB)         /* 64 gold partials per batch */
#define BP    132                    /* beta pitch: (4i+kg) and (4i+3kg+c) injective mod 32 */
#define PS    129                    /* potS pitch: bank (i+w) -> conflict-free */

// ---------------- device scratch (no allocations allowed) ----------------
__device__ float g_pot[CELLS];            // row-major pot[b][i][j] (upper triangle valid)
__device__ float g_goldpart[BB * PARTS];  // per-block gold partial sums
__device__ float g_margin[BB];
__device__ unsigned g_count;              // wrapping completion counter (replay-safe)

// float <-> monotonic u32 key for redux.sync.max.u32
__device__ __forceinline__ unsigned f2key(float x) {
    int i = __float_as_int(x);
    return (unsigned)i ^ ((unsigned)(i >> 31) | 0x80000000u);
}
__device__ __forceinline__ float key2f(unsigned k) {
    unsigned u = (k & 0x80000000u) ? (k ^ 0x80000000u) : ~k;
    return __int_as_float((int)u);
}

// ---------------- K1: pot (row-major, upper tri only) + gold partials ----------------
// One warp per 16 consecutive cells (one (b,i) row segment; lane == label, L==32).
//   gold contribution per cell = x_g - x_0; summed as (sum shfl(x,g)) - (lane0's sum x)
//   pot = max_l(x_l + (l==g ? 0:1)) - x_0    (upper-triangle cells only)
// The -1e9 augment on (b,0,len-1,0) is patched in K2 (smem).
__global__ void __launch_bounds__(512) k1_pot(const float* __restrict__ logits,
                                              const void* __restrict__ labels) {
    const int warp = threadIdx.x >> 5;
    const int lane = threadIdx.x & 31;

    // labels dtype detection (uniform, deterministic): int64 values lie in [-100,32)
    long long v0 = ((const long long*)labels)[lane];
    const bool lab64 = (__ballot_sync(FULL, v0 >= -100 && v0 < 32) == FULL);

    const int c0 = (blockIdx.x * K1_WPB + warp) * K1_CPW;
    int labv = 0;
    if (lane < K1_CPW) {
        labv = lab64 ? (int)((const long long*)labels)[c0 + lane]
                     : ((const int*)labels)[c0 + lane];
        if (labv < 0) labv = 0;
    }

    // front-batched loads (MLP = 16, 2KB contiguous per warp)
    float x[K1_CPW];
    const float* base = logits + (size_t)c0 * LL;
#pragma unroll
    for (int q = 0; q < K1_CPW; ++q) x[q] = base[q * LL + lane];

    const int ii = (c0 >> 7) & 127;   // all 16 cells share row ii
    const int j0 = c0 & 127;

    float goldg = 0.0f, mysum = 0.0f, potq = 0.0f;
#pragma unroll
    for (int q = 0; q < K1_CPW; ++q) {
        int g = __shfl_sync(FULL, labv, q);
        goldg += __shfl_sync(FULL, x[q], g);   // warp-uniform
        mysum += x[q];                          // lane 0's copy = sum of x_0
        if (j0 + q >= ii) {                     // upper triangle only (warp-uniform)
            unsigned r = __reduce_max_sync(FULL, f2key(x[q] + (lane == g ? 0.0f : 1.0f)));
            float m0 = __shfl_sync(FULL, x[q], 0);
            if (lane == q) potq = key2f(r) - m0;
        }
    }
    if (lane < K1_CPW && j0 + lane >= ii) g_pot[c0 + lane] = potq;  // coalesced 64B

    __shared__ float sh[K1_WPB];
    if (lane == 0) sh[warp] = goldg - mysum;
    __syncthreads();
    if (threadIdx.x == 0) {
        float s = 0.0f;
#pragma unroll
        for (int t = 0; t < K1_WPB; ++t) s += sh[t];   // fixed order -> deterministic
        g_goldpart[blockIdx.x] = s;                     // blockIdx = b*PARTS + local
    }
}

// ---------------- K2: per-batch max-plus CKY ----------------
// beta[i][w] = potS[i][w] + max_{k<w} beta[i][k] + beta[i+k+1][w-1-k]
// 512 threads: i = tid>>2, kg = tid&3 (4-way k split, 2-shfl reduce).
// Pitch BP=132 -> both LDS patterns conflict-free (verified injective mod 32).
// potS[i][w] pitch 129: coalesced staging, conflict-free broadcast reads.
__global__ void __launch_bounds__(512) k2_cky(const float* __restrict__ logits,
                                              const void* __restrict__ labels,
                                              float* __restrict__ out) {
    extern __shared__ float smem[];
    float* beta = smem;               // NN_ * BP floats
    float* potS = smem + NN_ * BP;    // NN_ * PS floats
    __shared__ float red[PARTS];

    const int b   = blockIdx.x;
    const int tid = threadIdx.x;

    long long v = ((const long long*)labels)[tid & 31];
    const bool lab64 = (__ballot_sync(FULL, v >= -100 && v < 32) == FULL);

    // sequence length = count(labels[b,0,:] != -100)
    int pflag = 0;
    if (tid < NN_) {
        size_t idx = ((size_t)b << 14) + tid;
        int lab = lab64 ? (int)((const long long*)labels)[idx]
                        : ((const int*)labels)[idx];
        pflag = (lab != -100);
    }
    const int len = __syncthreads_count(pflag);

    if (tid < PARTS) red[tid] = g_goldpart[b * PARTS + tid];

    // ---- stage potS[i][w] = pot[i][i+w] (coalesced within each row) ----
    const float* potb = g_pot + ((size_t)b << 14);
#pragma unroll
    for (int t = tid; t < NN2; t += 512) {
        int i = t >> 7, w = t & 127;
        potS[i * PS + w] = (i + w < NN_) ? potb[(i << 7) + i + w] : NEGV;
    }
    __syncthreads();

    // ---- patch pot[b,0,len-1] with the extra -1e9 augment on label 0 ----
    if (tid < 32) {
        const int j = len - 1;
        size_t cell = ((size_t)b << 14) + j;
        int g = lab64 ? (int)((const long long*)labels)[cell]
                      : ((const int*)labels)[cell];
        if (g < 0) g = 0;
        float xx = logits[cell * LL + tid];
        float m0 = __shfl_sync(FULL, xx, 0);
        float cand = (xx - m0) + (tid == g ? 0.0f : 1.0f)
                               + (tid == 0 ? NEGV : 0.0f);
#pragma unroll
        for (int o = 16; o > 0; o >>= 1)
            cand = fmaxf(cand, __shfl_xor_sync(FULL, cand, o));
        if (tid == 0) potS[j] = cand;          // potS[0][len-1]
    }
    __syncthreads();

    // ---- width 0 ----
    if (tid < NN_) beta[tid * BP] = potS[tid * PS];
    __syncthreads();

    const int i  = tid >> 2;
    const int kg = tid & 3;

    for (int w = 1; w < NN_; ++w) {
        const bool act = (i < NN_ - w);
        float potv = 0.0f;
        float a0 = -1e30f, a1 = -1e30f, a2 = -1e30f, a3 = -1e30f;
        if (act) {
            potv = potS[i * PS + w];
            const float* pL = beta + i * BP + kg;                       // beta[i][k]
            const float* pR = beta + (i + kg + 1) * BP + (w - 1 - kg);  // beta[i+k+1][w-1-k]
            int k = kg;
            for (; k + 12 < w; k += 16) {                 // 4 k-ops per iter
                a0 = fmaxf(a0, pL[0]  + pR[0]);
                a1 = fmaxf(a1, pL[4]  + pR[524]);
                a2 = fmaxf(a2, pL[8]  + pR[1048]);
                a3 = fmaxf(a3, pL[12] + pR[1572]);
                pL += 16; pR += 2096;                     // 4*(4*BP-4)
            }
            for (; k < w; k += 4) {
                a0 = fmaxf(a0, pL[0] + pR[0]);
                pL += 4; pR += 524;                       // 4*BP-4
            }
        }
        float m = fmaxf(fmaxf(a0, a1), fmaxf(a2, a3));
        m = fmaxf(m, __shfl_xor_sync(FULL, m, 1));        // within 4-lane group
        m = fmaxf(m, __shfl_xor_sync(FULL, m, 2));
        if (act && kg == 0) beta[i * BP + w] = m + potv;
        __syncthreads();
    }

    // ---- margin + deterministic final reduce ----
    if (tid == 0) {
        float gold = 0.0f;
#pragma unroll
        for (int t = 0; t < PARTS; ++t) gold += red[t];   // fixed order
        float pred = beta[len - 1];                        // beta[0][len-1]
        g_margin[b] = fmaxf(pred - gold, 0.0f);
        __threadfence();
        unsigned old = atomicInc(&g_count, BB - 1);        // wraps -> replay/graph-safe
        if (old == BB - 1) {                               // last block: fixed-order mean
            float s = 0.0f;
            volatile float* gm = g_margin;
#pragma unroll
            for (int t = 0; t < BB; ++t) s += gm[t];
            out[0] = s * (1.0f / (float)BB);
        }
    }
}

// ---------------- launch ----------------
extern "C" void kernel_launch(void* const* d_in, const int* in_sizes, int n_in,
                              void* d_out, int out_size) {
    const float* logits = (const float*)d_in[0];
    const void*  labels = d_in[1];

    const int smem_bytes = (NN_ * BP + NN_ * PS) * (int)sizeof(float); // 133,632
    cudaFuncSetAttribute(k2_cky, cudaFuncAttributeMaxDynamicSharedMemorySize, smem_bytes);

    k1_pot<<<K1_BLOCKS, 512>>>(logits, labels);
    k2_cky<<<BB, 512, smem_bytes>>>(logits, labels, (float*)d_out);
}

// round 8
// speedup vs baseline: 2.0168x; 1.2960x over previous
#include <cuda_runtime.h>
#include <cuda_bf16.h>

#define FULL 0xffffffffu
#define NEGV -1000000000.0f

// Problem shape (fixed): B=64, N=128, L=32
#define BB    64
#define NN_   128
#define LL    32
#define NN2   (NN_ * NN_)            /* 16384 cells per batch */
#define CELLS (BB * NN2)             /* 1,048,576 cells        */
#define K1_CPB 256                   /* cells per K1 block (8 warps x 32) */
#define K1_BLOCKS (CELLS / K1_CPB)   /* 4096                   */
#define PARTS (NN2 / K1_CPB)         /* 64 gold partials per batch */
#define PA    132                    /* beta pitch */
#define BROWS 136                    /* beta rows incl. 8 NEG pad rows */
#define PSP   129                    /* potS pitch */
#define TT    8                      /* width-tile size */

// ---------------- device scratch (no allocations allowed) ----------------
__device__ float g_pot[CELLS];            // row-major pot[b][i][j] (upper triangle valid)
__device__ float g_goldpart[BB * PARTS];  // per-block gold partial sums
__device__ float g_margin[BB];
__device__ unsigned g_count;              // wrapping completion counter (replay-safe)

// ---------------- K1: pot (row-major, upper tri only) + gold partials ----------------
// 8 warps x 32 cells. Warp stages 4KB of logits into smem (pitch 33 = conflict-free),
// then each lane processes its own cell: x_g read, slot g := NEG, 31-fmax tree.
//   pot  = max(maxall_excl_g + 1, x_g) - x_0
//   gold = x_g - x_0  (summed warp-wide via fixed shfl tree -> deterministic)
// The -1e9 augment on (b,0,len-1,0) is patched in K2.
__global__ void __launch_bounds__(256) k1_pot(const float* __restrict__ logits,
                                              const void* __restrict__ labels) {
    __shared__ float stage[8][32 * 33];
    __shared__ float gsh[8];
    const int warp = threadIdx.x >> 5;
    const int lane = threadIdx.x & 31;

    // labels dtype detection (uniform, deterministic): int64 values lie in [-100,32)
    long long v0 = ((const long long*)labels)[lane];
    const bool lab64 = (__ballot_sync(FULL, v0 >= -100 && v0 < 32) == FULL);

    const int c0 = (blockIdx.x * 8 + warp) * 32;
    const int c  = c0 + lane;                       // this lane's cell
    int g = lab64 ? (int)((const long long*)labels)[c]
                  : ((const int*)labels)[c];
    if (g < 0) g = 0;

    // stage 32 cells x 32 labels (coalesced LDG.128, conflict-free scalar STS)
    const float4* src = (const float4*)(logits + (size_t)c0 * LL);
    float* sw = stage[warp];
#pragma unroll
    for (int j = 0; j < 8; ++j) {
        float4 f = src[lane + 32 * j];
        int p = lane + 32 * j;                      // float4 index
        int cell = p >> 3, off = (p & 7) << 2;
        float* d = sw + cell * 33 + off;
        d[0] = f.x; d[1] = f.y; d[2] = f.z; d[3] = f.w;
    }
    __syncwarp();

    float* row = sw + lane * 33;
    float xg = row[g];
    float x0 = row[0];
    row[g] = NEGV;                                  // exclude gold label from the max
    float a0 = row[0], a1 = row[1], a2 = row[2], a3 = row[3];
#pragma unroll
    for (int t = 4; t < 32; t += 4) {
        a0 = fmaxf(a0, row[t]);
        a1 = fmaxf(a1, row[t + 1]);
        a2 = fmaxf(a2, row[t + 2]);
        a3 = fmaxf(a3, row[t + 3]);
    }
    float mx = fmaxf(fmaxf(a0, a1), fmaxf(a2, a3));
    float pot = fmaxf(mx + 1.0f, xg) - x0;

    const int ii = (c0 >> 7) & 127;                 // row index (32 | 128 -> one row/warp)
    const int j  = c & 127;
    if (j >= ii) g_pot[c] = pot;                    // upper triangle only, coalesced

    float gs = xg - x0;                             // gold contribution
#pragma unroll
    for (int o = 16; o; o >>= 1) gs += __shfl_xor_sync(FULL, gs, o);
    if (lane == 0) gsh[warp] = gs;
    __syncthreads();
    if (threadIdx.x == 0) {
        float s = 0.0f;
#pragma unroll
        for (int t = 0; t < 8; ++t) s += gsh[t];    // fixed order -> deterministic
        g_goldpart[blockIdx.x] = s;                 // blockIdx = b*PARTS + local
    }
}

// ---------------- K2: per-batch tiled max-plus CKY ----------------
// beta[i][w] = potS[i][w] + max_{k<w} beta[i][k] + beta[i+k+1][w-1-k]
// Tiles of TT=8 widths. Bulk phase (barrier-free): P(i,s) over k=0..W using only
// old data; NEG-initialized future slots auto-mask; concurrent fixup stores only
// add valid terms (max idempotent -> benign race). Fixup: 8 sequential steps/tile.
// Mapping: lane l = 4*ir + sg; row i = rb(warp)*8 + ir; lane owns s in {sg+1, sg+5}.
// Banks: A-read = 8-way broadcast (4ir+k); s-reads = {4ir+sg} all distinct. Verified.
__global__ void __launch_bounds__(512) k2_cky(const float* __restrict__ logits,
                                              const void* __restrict__ labels,
                                              float* __restrict__ out) {
    extern __shared__ float smem[];
    float* beta = smem;                    // BROWS * PA floats (rows 128..135 = NEG pad)
    float* potS = smem + BROWS * PA;       // NN_ * PSP floats
    __shared__ float red[PARTS];

    const int b    = blockIdx.x;
    const int tid  = threadIdx.x;
    const int warp = tid >> 5;
    const int lane = tid & 31;
    const int ir   = lane >> 2;
    const int sg   = lane & 3;
    const int rb   = (warp < 8) ? warp : (23 - warp);   // pair-reversed row blocks
    const int i    = rb * 8 + ir;

    long long v = ((const long long*)labels)[lane];
    const bool lab64 = (__ballot_sync(FULL, v >= -100 && v < 32) == FULL);

    // sequence length = count(labels[b,0,:] != -100)
    int pflag = 0;
    if (tid < NN_) {
        size_t idx = ((size_t)b << 14) + tid;
        int lab = lab64 ? (int)((const long long*)labels)[idx]
                        : ((const int*)labels)[idx];
        pflag = (lab != -100);
    }
    const int len = __syncthreads_count(pflag);

    if (tid < PARTS) red[tid] = g_goldpart[b * PARTS + tid];

    // ---- NEG-init beta (incl. pad rows) + stage potS[i][w] = pot[i][i+w] ----
    {
        float4* b4 = (float4*)beta;
        const float4 n4 = make_float4(NEGV, NEGV, NEGV, NEGV);
        for (int t = tid; t < BROWS * PA / 4; t += 512) b4[t] = n4;
        const float* potb = g_pot + ((size_t)b << 14);
        for (int t = tid; t < NN2; t += 512) {
            int ri = t >> 7, w = t & 127;
            potS[ri * PSP + w] = (ri + w < NN_) ? potb[(ri << 7) + ri + w] : NEGV;
        }
    }
    __syncthreads();

    // ---- patch pot[b,0,len-1] with the extra -1e9 augment on label 0 ----
    if (tid < 32) {
        const int jj = len - 1;
        size_t cell = ((size_t)b << 14) + jj;
        int g = lab64 ? (int)((const long long*)labels)[cell]
                      : ((const int*)labels)[cell];
        if (g < 0) g = 0;
        float xx = logits[cell * LL + tid];
        float m0 = __shfl_sync(FULL, xx, 0);
        float cand = (xx - m0) + (tid == g ? 0.0f : 1.0f)
                               + (tid == 0 ? NEGV : 0.0f);
#pragma unroll
        for (int o = 16; o > 0; o >>= 1)
            cand = fmaxf(cand, __shfl_xor_sync(FULL, cand, o));
        if (tid == 0) potS[jj] = cand;          // potS[0][len-1]
    }
    __syncthreads();

    // ---- width 0 ----
    if (tid < NN_) beta[tid * PA] = potS[tid * PSP];
    __syncthreads();

    // ---- tile loop ----
    for (int W = 0; W < NN_; W += TT) {
        // Bulk: acc0 -> s = sg+1, acc1 -> s = sg+5 (old x old region, no syncs)
        float acc0 = NEGV, acc1 = NEGV;
        if (rb * 8 <= 126 - W) {                 // warp has at least one active row
            const float* ap = beta + i * PA;
            const float* p2 = beta + (i + 1) * PA + W + sg;  // term2 at s=sg+1, k=0
#pragma unroll 4
            for (int k = 0; k <= W; ++k) {
                float a = ap[k];
                acc0 = fmaxf(acc0, a + p2[0]);
                acc1 = fmaxf(acc1, a + p2[4]);
                p2 += PA - 1;
            }
        }
        // Fixup: TT sequential steps, each completes width w = W+s
#pragma unroll
        for (int s = 1; s <= TT; ++s) {
            const int w = W + s;
            const bool act = (i <= NN_ - 1 - w);
            float m = (sg == ((s - 1) & 3)) ? (((s - 1) < 4) ? acc0 : acc1) : NEGV;
            if (act) {
                for (int t = sg; t < 2 * (s - 1); t += 4) {
                    int k = (t < s - 1) ? t : (W + 1 + t - (s - 1));
                    m = fmaxf(m, beta[i * PA + k] + beta[(i + k + 1) * PA + (w - 1 - k)]);
                }
            } else {
                m = NEGV;
            }
            m = fmaxf(m, __shfl_xor_sync(FULL, m, 1));
            m = fmaxf(m, __shfl_xor_sync(FULL, m, 2));
            if (act && sg == 0) beta[i * PA + w] = m + potS[i * PSP + w];
            __syncthreads();
        }
    }

    // ---- margin + deterministic final reduce ----
    if (tid == 0) {
        float gold = 0.0f;
#pragma unroll
        for (int t = 0; t < PARTS; ++t) gold += red[t];   // fixed order
        float pred = beta[len - 1];                        // beta[0][len-1]
        g_margin[b] = fmaxf(pred - gold, 0.0f);
        __threadfence();
        unsigned old = atomicInc(&g_count, BB - 1);        // wraps -> replay/graph-safe
        if (old == BB - 1) {                               // last block: fixed-order mean
            float s = 0.0f;
            volatile float* gm = g_margin;
#pragma unroll
            for (int t = 0; t < BB; ++t) s += gm[t];
            out[0] = s * (1.0f / (float)BB);
        }
    }
}

// ---------------- launch ----------------
extern "C" void kernel_launch(void* const* d_in, const int* in_sizes, int n_in,
                              void* d_out, int out_size) {
    const float* logits = (const float*)d_in[0];
    const void*  labels = d_in[1];

    const int smem_bytes = (BROWS * PA + NN_ * PSP) * (int)sizeof(float); // 137,856
    cudaFuncSetAttribute(k2_cky, cudaFuncAttributeMaxDynamicSharedMemorySize, smem_bytes);

    k1_pot<<<K1_BLOCKS, 256>>>(logits, labels);
    k2_cky<<<BB, 512, smem_bytes>>>(logits, labels, (float*)d_out);
}